// round 1
// baseline (speedup 1.0000x reference)
#include <cuda_runtime.h>

#define Bq   128
#define Dq   128
#define Nq   16384
#define NCq  100
#define TILE 128
#define NBLKS (Nq / TILE)   /* 128 main blocks */

// ---- static device scratch (no allocations allowed) ----
__device__ float g_Xp[Bq * Dq];
__device__ float g_y2[Bq];
__device__ float g_x2[Nq];
__device__ float g_Spart[NBLKS * Bq];
__device__ float g_Opart[NBLKS * Bq * NCq];   // ~6.55 MB

// =====================================================================
// Kernel 1: project X onto the ball (Xp, y2) and compute x2[n] = ||A[n]||^2
// blocks [0,16): X projection, 1 row per warp
// blocks [16,272): x2, 64 rows per block (8 rows per warp)
// =====================================================================
__global__ void prep_kernel(const float* __restrict__ X,
                            const float* __restrict__ A) {
    const int warp = threadIdx.x >> 5;
    const int lane = threadIdx.x & 31;

    if (blockIdx.x < 16) {
        const int r = blockIdx.x * 8 + warp;   // 16*8 = 128 rows
        float v[4];
        float ss = 0.f;
#pragma unroll
        for (int t = 0; t < 4; t++) {
            v[t] = X[r * Dq + lane + 32 * t];
            ss += v[t] * v[t];
        }
#pragma unroll
        for (int off = 16; off > 0; off >>= 1)
            ss += __shfl_xor_sync(0xffffffffu, ss, off);
        float norm = fmaxf(sqrtf(ss), 1e-15f);
        const float maxn = 1.0f - 4e-3f;
        float scale = (norm > maxn) ? (maxn / norm) : 1.0f;
        float ss2 = 0.f;
#pragma unroll
        for (int t = 0; t < 4; t++) {
            float p = v[t] * scale;
            g_Xp[r * Dq + lane + 32 * t] = p;
            ss2 += p * p;
        }
#pragma unroll
        for (int off = 16; off > 0; off >>= 1)
            ss2 += __shfl_xor_sync(0xffffffffu, ss2, off);
        if (lane == 0) g_y2[r] = ss2;
    } else {
        const int base = (blockIdx.x - 16) * 64;
#pragma unroll
        for (int r = 0; r < 8; r++) {
            const int row = base + r * 8 + warp;
            float ss = 0.f;
#pragma unroll
            for (int t = 0; t < 4; t++) {
                float v = A[row * Dq + lane + 32 * t];
                ss += v * v;
            }
#pragma unroll
            for (int off = 16; off > 0; off >>= 1)
                ss += __shfl_xor_sync(0xffffffffu, ss, off);
            if (lane == 0) g_x2[row] = ss;
        }
    }
}

// =====================================================================
// Kernel 2: per 128-row tile of prototypes:
//   GEMM1 dots -> fused Poincare-distance weight epilogue ->
//   GEMM2 partials (W^T @ C) and partial softmax denominators.
// smem (floats): As/Xs transposed [128][132], Cs [128][112], x2s/y2s [128]
// =====================================================================
#define SMEM_FLOATS (2 * 128 * 132 + 128 * 112 + 256)
#define SMEM_BYTES  (SMEM_FLOATS * 4)

__global__ __launch_bounds__(256, 1)
void main_kernel(const float* __restrict__ A, const float* __restrict__ C) {
    extern __shared__ float sm[];
    float* As  = sm;                    // [k][n], stride 132
    float* Xs  = sm + 128 * 132;        // [k][b], stride 132
    float* Cs  = sm + 2 * 128 * 132;    // [n][c], stride 112 (c>=100 zero)
    float* x2s = Cs + 128 * 112;
    float* y2s = x2s + 128;
    float* Ws  = As;                    // reuse As region: [n][b], stride 132

    const int tid = threadIdx.x;
    const int n0g = blockIdx.x * TILE;

    // loads (coalesced global; transposed smem store)
    for (int idx = tid; idx < TILE * Dq; idx += 256) {
        int n = idx >> 7;
        int k = idx & 127;
        As[k * 132 + n] = A[(n0g + n) * Dq + k];
        Xs[k * 132 + n] = g_Xp[idx];
    }
    for (int idx = tid; idx < TILE * 112; idx += 256) {
        int n = idx / 112;
        int c = idx - n * 112;
        Cs[idx] = (c < NCq) ? C[(n0g + n) * NCq + c] : 0.0f;
    }
    if (tid < 128) {
        x2s[tid] = g_x2[n0g + tid];
        y2s[tid] = g_y2[tid];
    }
    __syncthreads();

    const int tx  = tid & 15;
    const int ty  = tid >> 4;
    const int nn0 = ty * 8;
    const int bb0 = tx * 8;

    // ---------------- GEMM1: dots[n][b] ----------------
    float acc[8][8];
#pragma unroll
    for (int i = 0; i < 8; i++)
#pragma unroll
        for (int j = 0; j < 8; j++) acc[i][j] = 0.f;

#pragma unroll 4
    for (int k = 0; k < 128; k++) {
        float4 a0 = *(const float4*)(As + k * 132 + nn0);
        float4 a1 = *(const float4*)(As + k * 132 + nn0 + 4);
        float4 x0 = *(const float4*)(Xs + k * 132 + bb0);
        float4 x1 = *(const float4*)(Xs + k * 132 + bb0 + 4);
        float av[8] = {a0.x, a0.y, a0.z, a0.w, a1.x, a1.y, a1.z, a1.w};
        float xv[8] = {x0.x, x0.y, x0.z, x0.w, x1.x, x1.y, x1.z, x1.w};
#pragma unroll
        for (int i = 0; i < 8; i++)
#pragma unroll
            for (int j = 0; j < 8; j++)
                acc[i][j] = fmaf(av[i], xv[j], acc[i][j]);
    }
    __syncthreads();   // all GEMM1 smem reads done before Ws overwrites As

    // ---------------- epilogue: softmin weights ----------------
    // w = exp(-dist/4) = ((1-z)/(1+z))^(1/4),  z = clip(||diff||, <= 1-1e-7)
#pragma unroll
    for (int i = 0; i < 8; i++) {
        float x2   = x2s[nn0 + i];
        float beta = 1.0f - x2;
#pragma unroll
        for (int j = 0; j < 8; j++) {
            float y2    = y2s[bb0 + j];
            float xy    = -acc[i][j];
            float t     = fmaf(2.0f, xy, 1.0f);          // 1 + 2xy
            float alpha = t + y2;
            float den   = fmaxf(fmaf(x2, y2, t), 1e-15f);
            float num2  = alpha * alpha * x2
                        + 2.0f * alpha * beta * xy
                        + beta * beta * y2;
            num2 = fmaxf(num2, 0.0f);
            float z = sqrtf(num2) / den;
            z = fminf(z, 0.9999999f);                    // 1 - 1e-7 clip
            float r = (1.0f - z) / (1.0f + z);
            acc[i][j] = sqrtf(sqrtf(r));                 // r^(1/4)
        }
    }
#pragma unroll
    for (int i = 0; i < 8; i++) {
        *(float4*)(Ws + (nn0 + i) * 132 + bb0) =
            make_float4(acc[i][0], acc[i][1], acc[i][2], acc[i][3]);
        *(float4*)(Ws + (nn0 + i) * 132 + bb0 + 4) =
            make_float4(acc[i][4], acc[i][5], acc[i][6], acc[i][7]);
    }
    __syncthreads();

    // partial softmax denominators S[b] = sum_n w[n][b]
    if (tid < 128) {
        float s = 0.f;
#pragma unroll 8
        for (int n = 0; n < 128; n++) s += Ws[n * 132 + tid];
        g_Spart[blockIdx.x * Bq + tid] = s;
    }

    // ---------------- GEMM2: O[b][c] = sum_n w[n][b] * C[n][c] ----------------
    const int c0 = tx * 7;   // 16*7 = 112 >= 100, guarded at store
    const int b0 = ty * 8;
    float o[8][7];
#pragma unroll
    for (int i = 0; i < 8; i++)
#pragma unroll
        for (int jj = 0; jj < 7; jj++) o[i][jj] = 0.f;

#pragma unroll 2
    for (int n = 0; n < 128; n++) {
        float4 w0 = *(const float4*)(Ws + n * 132 + b0);
        float4 w1 = *(const float4*)(Ws + n * 132 + b0 + 4);
        float wv[8] = {w0.x, w0.y, w0.z, w0.w, w1.x, w1.y, w1.z, w1.w};
        float cv[7];
#pragma unroll
        for (int jj = 0; jj < 7; jj++) cv[jj] = Cs[n * 112 + c0 + jj];
#pragma unroll
        for (int i = 0; i < 8; i++)
#pragma unroll
            for (int jj = 0; jj < 7; jj++)
                o[i][jj] = fmaf(wv[i], cv[jj], o[i][jj]);
    }

#pragma unroll
    for (int i = 0; i < 8; i++)
#pragma unroll
        for (int jj = 0; jj < 7; jj++)
            if (c0 + jj < NCq)
                g_Opart[(blockIdx.x * Bq + b0 + i) * NCq + c0 + jj] = o[i][jj];
}

// =====================================================================
// Kernel 3: deterministic reduction over the 128 tile-partials + normalize
// =====================================================================
__global__ void reduce_kernel(float* __restrict__ out) {
    const int idx = blockIdx.x * 256 + threadIdx.x;
    if (idx >= Bq * NCq) return;
    const int b = idx / NCq;
    const int c = idx - b * NCq;
    float s = 0.f, o = 0.f;
#pragma unroll 4
    for (int kb = 0; kb < NBLKS; kb++) {
        o += g_Opart[(kb * Bq + b) * NCq + c];
        s += g_Spart[kb * Bq + b];
    }
    out[idx] = o / s;
}

// =====================================================================
extern "C" void kernel_launch(void* const* d_in, const int* in_sizes, int n_in,
                              void* d_out, int out_size) {
    (void)in_sizes; (void)n_in; (void)out_size;
    const float* X = (const float*)d_in[0];   // [128,128]
    const float* A = (const float*)d_in[1];   // [16384,1,128]
    const float* C = (const float*)d_in[2];   // [16384,100]
    float* out = (float*)d_out;               // [128,100] fp32

    cudaFuncSetAttribute(main_kernel,
                         cudaFuncAttributeMaxDynamicSharedMemorySize,
                         SMEM_BYTES);

    prep_kernel<<<16 + 256, 256>>>(X, A);
    main_kernel<<<NBLKS, 256, SMEM_BYTES>>>(A, C);
    reduce_kernel<<<(Bq * NCq + 255) / 256, 256>>>(out);
}

// round 4
// speedup vs baseline: 1.7632x; 1.7632x over previous
#include <cuda_runtime.h>
#include <cstdint>

#define NCq   100
#define NBLKS 128
#define PADA  132      /* As / Xs / Ws row stride (floats) */
#define PADC  120      /* Cs row stride (floats) */

// ---- static device scratch (no allocations allowed) ----
__device__ float g_Spart[NBLKS * 128];
__device__ float g_Opart[NBLKS * 128 * NCq];   // 6.55 MB

// smem layout (floats)
#define XS_OFF  (128 * PADA)
#define CS_OFF  (2 * 128 * PADA)
#define X2_OFF  (CS_OFF + 128 * PADC)
#define Y2_OFF  (X2_OFF + 128)
#define SMEM_FLOATS (Y2_OFF + 128)
#define SMEM_BYTES  (SMEM_FLOATS * 4)   /* 197632 B */

// ============================ helpers ============================
__device__ __forceinline__ float tf32r(float a) {
    uint32_t r;                       // tf32 cvt needs a .b32 destination
    asm("cvt.rna.tf32.f32 %0, %1;" : "=r"(r) : "f"(a));
    return __uint_as_float(r);
}
__device__ __forceinline__ float fsqrt_ap(float x) {
    float r; asm("sqrt.approx.f32 %0, %1;" : "=f"(r) : "f"(x)); return r;
}
__device__ __forceinline__ float frsqrt_ap(float x) {
    float r; asm("rsqrt.approx.f32 %0, %1;" : "=f"(r) : "f"(x)); return r;
}
// D += A(16x8,row) * B(8x8,col)   tf32
__device__ __forceinline__ void mma8(float* d, float a0, float a1, float a2, float a3,
                                     float b0, float b1) {
    asm volatile(
        "mma.sync.aligned.m16n8k8.row.col.f32.tf32.tf32.f32 "
        "{%0,%1,%2,%3}, {%4,%5,%6,%7}, {%8,%9}, {%0,%1,%2,%3};"
        : "+f"(d[0]), "+f"(d[1]), "+f"(d[2]), "+f"(d[3])
        : "r"(__float_as_uint(a0)), "r"(__float_as_uint(a1)),
          "r"(__float_as_uint(a2)), "r"(__float_as_uint(a3)),
          "r"(__float_as_uint(b0)), "r"(__float_as_uint(b1)));
}

// ============================ main kernel ============================
__global__ __launch_bounds__(256, 1)
void main_kernel(const float* __restrict__ X, const float* __restrict__ A,
                 const float* __restrict__ C) {
    extern __shared__ float sm[];
    float* As  = sm;                 // [n][k] pad 132 (tf32)   -> later Ws [b][n]
    float* Xs  = sm + XS_OFF;        // [b][k] pad 132 (tf32)
    float* Cs  = sm + CS_OFF;        // [n][c] pad 120 (tf32), col100=1, 101..119=0
    float* x2s = sm + X2_OFF;
    float* y2s = sm + Y2_OFF;

    const int tid = threadIdx.x;
    const int w   = tid >> 5;
    const int l   = tid & 31;
    const int g   = l >> 2;          // 0..7
    const int tg  = l & 3;           // 0..3
    const int n0  = blockIdx.x * 128;

    // ---------------- load + project + transpose ----------------
#pragma unroll
    for (int it = 0; it < 16; it++) {
        const int r = it * 8 + w;
        // A row -> As[r][*], x2
        float4 va = ((const float4*)(A + (size_t)(n0 + r) * 128))[l];
        float sa = va.x * va.x + va.y * va.y + va.z * va.z + va.w * va.w;
#pragma unroll
        for (int off = 16; off > 0; off >>= 1)
            sa += __shfl_xor_sync(0xffffffffu, sa, off);
        if (l == 0) x2s[r] = sa;
        *(float4*)&As[r * PADA + l * 4] =
            make_float4(tf32r(va.x), tf32r(va.y), tf32r(va.z), tf32r(va.w));

        // X row -> project -> Xs[r][*], y2
        float4 vx = ((const float4*)(X + (size_t)r * 128))[l];
        float sx = vx.x * vx.x + vx.y * vx.y + vx.z * vx.z + vx.w * vx.w;
#pragma unroll
        for (int off = 16; off > 0; off >>= 1)
            sx += __shfl_xor_sync(0xffffffffu, sx, off);
        float norm  = fmaxf(sqrtf(sx), 1e-15f);
        const float maxn = 1.0f - 4e-3f;
        float scale = (norm > maxn) ? (maxn / norm) : 1.0f;
        if (l == 0) y2s[r] = sx * scale * scale;
        vx.x *= scale; vx.y *= scale; vx.z *= scale; vx.w *= scale;
        *(float4*)&Xs[r * PADA + l * 4] =
            make_float4(tf32r(vx.x), tf32r(vx.y), tf32r(vx.z), tf32r(vx.w));

        // C row -> Cs[r][*] (K-major for GEMM2 B), ones col at 100
        float4 vc = make_float4(0.f, 0.f, 0.f, 0.f);
        if (l < 25)      vc = ((const float4*)(C + (size_t)(n0 + r) * NCq))[l];
        else if (l == 25) vc = make_float4(1.0f, 0.f, 0.f, 0.f);
        if (l < 30)
            *(float4*)&Cs[r * PADC + l * 4] =
                make_float4(tf32r(vc.x), tf32r(vc.y), tf32r(vc.z), tf32r(vc.w));
    }
    __syncthreads();

    // ---------------- GEMM1: D1[n][b] = A @ Xp^T ----------------
    // warp tile: 32n x 64b   (wn = w>>1 in 0..3, wb = w&1)
    const int wn = w >> 1, wb = w & 1;
    const float* Ab = As + (wn * 32) * PADA;
    const float* Xb = Xs + (wb * 64) * PADA;

    float acc[2][8][4];
#pragma unroll
    for (int mt = 0; mt < 2; mt++)
#pragma unroll
        for (int bt = 0; bt < 8; bt++)
#pragma unroll
            for (int rr = 0; rr < 4; rr++) acc[mt][bt][rr] = 0.f;

#pragma unroll
    for (int ks = 0; ks < 16; ks++) {
        const int kc = ks * 8 + tg;
        float a0[2], a1[2], a2[2], a3[2];
#pragma unroll
        for (int mt = 0; mt < 2; mt++) {
            a0[mt] = Ab[(mt * 16 + g) * PADA + kc];
            a1[mt] = Ab[(mt * 16 + 8 + g) * PADA + kc];
            a2[mt] = Ab[(mt * 16 + g) * PADA + kc + 4];
            a3[mt] = Ab[(mt * 16 + 8 + g) * PADA + kc + 4];
        }
#pragma unroll
        for (int bt = 0; bt < 8; bt++) {
            float b0 = Xb[(bt * 8 + g) * PADA + kc];
            float b1 = Xb[(bt * 8 + g) * PADA + kc + 4];
            mma8(acc[0][bt], a0[0], a1[0], a2[0], a3[0], b0, b1);
            mma8(acc[1][bt], a0[1], a1[1], a2[1], a3[1], b0, b1);
        }
    }

    // ---------------- epilogue: dot -> w (in-place in acc) ----------------
    // w = (PxPy)^(1/4) * rsqrt(sqrt(den) + sqrt(||x-y||^2))
    float x2v[4], px4[4];
#pragma unroll
    for (int mt = 0; mt < 2; mt++)
#pragma unroll
        for (int h = 0; h < 2; h++) {
            float x2 = x2s[wn * 32 + mt * 16 + h * 8 + g];
            x2v[mt * 2 + h] = x2;
            px4[mt * 2 + h] = fsqrt_ap(fsqrt_ap(1.0f - x2));
        }
    float y2v[16], py4[16];
#pragma unroll
    for (int bt = 0; bt < 8; bt++)
#pragma unroll
        for (int j = 0; j < 2; j++) {
            float y2 = y2s[wb * 64 + bt * 8 + 2 * tg + j];
            y2v[bt * 2 + j] = y2;
            py4[bt * 2 + j] = fsqrt_ap(fsqrt_ap(1.0f - y2));
        }
#pragma unroll
    for (int mt = 0; mt < 2; mt++)
#pragma unroll
        for (int bt = 0; bt < 8; bt++)
#pragma unroll
            for (int rr = 0; rr < 4; rr++) {
                const int hi = rr >> 1, j = rr & 1;
                float dot = acc[mt][bt][rr];
                float x2  = x2v[mt * 2 + hi];
                float y2  = y2v[bt * 2 + j];
                float den = fmaf(x2, y2, fmaf(-2.0f, dot, 1.0f));
                float v2  = fmaxf(fmaf(-2.0f, dot, x2 + y2), 0.0f);
                float s   = fsqrt_ap(den) + fsqrt_ap(v2);
                float wq  = px4[mt * 2 + hi] * py4[bt * 2 + j] * frsqrt_ap(s);
                wq = fminf(fmaxf(wq, 0.015625f), 1.0f);   // z<=1-1e-7 clip / w<=1
                acc[mt][bt][rr] = tf32r(wq);
            }

    __syncthreads();   // all GEMM1 smem reads done before Ws overwrites As

    // store W transposed: Ws[b][n]  (alias of As)
    float* Ws = As;
#pragma unroll
    for (int mt = 0; mt < 2; mt++)
#pragma unroll
        for (int bt = 0; bt < 8; bt++) {
            const int nn = wn * 32 + mt * 16 + g;
            const int bb = wb * 64 + bt * 8 + 2 * tg;
            Ws[(bb)     * PADA + nn]     = acc[mt][bt][0];
            Ws[(bb + 1) * PADA + nn]     = acc[mt][bt][1];
            Ws[(bb)     * PADA + nn + 8] = acc[mt][bt][2];
            Ws[(bb + 1) * PADA + nn + 8] = acc[mt][bt][3];
        }
    __syncthreads();

    // ---------------- GEMM2: O[b][c] = W @ C  (N=112, col100 = S) ----------------
    // warp tile: 32b x 56c   (wb2 = w>>1, wc = w&1)
    const int wb2 = w >> 1, wc = w & 1;
    const float* Wb = Ws + (wb2 * 32) * PADA;

    float acc2[2][7][4];
#pragma unroll
    for (int mt = 0; mt < 2; mt++)
#pragma unroll
        for (int ct = 0; ct < 7; ct++)
#pragma unroll
            for (int rr = 0; rr < 4; rr++) acc2[mt][ct][rr] = 0.f;

#pragma unroll
    for (int ks = 0; ks < 16; ks++) {
        const int kc = ks * 8 + tg;
        float a0[2], a1[2], a2[2], a3[2];
#pragma unroll
        for (int mt = 0; mt < 2; mt++) {
            a0[mt] = Wb[(mt * 16 + g) * PADA + kc];
            a1[mt] = Wb[(mt * 16 + 8 + g) * PADA + kc];
            a2[mt] = Wb[(mt * 16 + g) * PADA + kc + 4];
            a3[mt] = Wb[(mt * 16 + 8 + g) * PADA + kc + 4];
        }
#pragma unroll
        for (int ct = 0; ct < 7; ct++) {
            const int col = wc * 56 + ct * 8 + g;
            float b0 = Cs[(kc)     * PADC + col];
            float b1 = Cs[(kc + 4) * PADC + col];
            mma8(acc2[0][ct], a0[0], a1[0], a2[0], a3[0], b0, b1);
            mma8(acc2[1][ct], a0[1], a1[1], a2[1], a3[1], b0, b1);
        }
    }

    // ---------------- store partials ----------------
    const size_t obase = (size_t)blockIdx.x * 128;
#pragma unroll
    for (int mt = 0; mt < 2; mt++)
#pragma unroll
        for (int ct = 0; ct < 7; ct++) {
            const int c = wc * 56 + ct * 8 + 2 * tg;
            const int b = wb2 * 32 + mt * 16 + g;
            if (c < NCq) {
                *(float2*)&g_Opart[(obase + b) * NCq + c] =
                    make_float2(acc2[mt][ct][0], acc2[mt][ct][1]);
                *(float2*)&g_Opart[(obase + b + 8) * NCq + c] =
                    make_float2(acc2[mt][ct][2], acc2[mt][ct][3]);
            } else if (c == NCq) {   // ones column -> softmax denominator
                g_Spart[obase + b]     = acc2[mt][ct][0];
                g_Spart[obase + b + 8] = acc2[mt][ct][2];
            }
        }
}

// ============================ reduction ============================
__global__ void reduce_kernel(float* __restrict__ out) {
    const int idx = blockIdx.x * 256 + threadIdx.x;
    if (idx >= 128 * NCq) return;
    const int b = idx / NCq;
    const int c = idx - b * NCq;
    float s = 0.f, o = 0.f;
#pragma unroll 4
    for (int kb = 0; kb < NBLKS; kb++) {
        o += g_Opart[(size_t)(kb * 128 + b) * NCq + c];
        s += g_Spart[kb * 128 + b];
    }
    out[idx] = o / s;
}

// ============================ launch ============================
extern "C" void kernel_launch(void* const* d_in, const int* in_sizes, int n_in,
                              void* d_out, int out_size) {
    (void)in_sizes; (void)n_in; (void)out_size;
    const float* X = (const float*)d_in[0];   // [128,128]
    const float* A = (const float*)d_in[1];   // [16384,1,128]
    const float* C = (const float*)d_in[2];   // [16384,100]
    float* out = (float*)d_out;               // [128,100] fp32

    cudaFuncSetAttribute(main_kernel,
                         cudaFuncAttributeMaxDynamicSharedMemorySize, SMEM_BYTES);

    main_kernel<<<NBLKS, 256, SMEM_BYTES>>>(X, A, C);
    reduce_kernel<<<(128 * NCq + 255) / 256, 256>>>(out);
}

// round 5
// speedup vs baseline: 2.3103x; 1.3103x over previous
#include <cuda_runtime.h>
#include <cstdint>

#define NCq   100
#define NBLKS 128
#define PADA  132      /* As / Xs / Ws row stride (floats) */
#define PADC  120      /* Cs row stride (floats) */

// ---- static device scratch (no allocations allowed) ----
__device__ float g_Spart[NBLKS * 128];
__device__ float g_Opart[NBLKS * 128 * NCq];   // 6.55 MB

// smem layout (floats)
#define XS_OFF  (128 * PADA)
#define CS_OFF  (2 * 128 * PADA)
#define X2_OFF  (CS_OFF + 128 * PADC)
#define Y2_OFF  (X2_OFF + 128)
#define SMEM_FLOATS (Y2_OFF + 128)
#define SMEM_BYTES  (SMEM_FLOATS * 4)   /* 197632 B */

// ============================ helpers ============================
__device__ __forceinline__ float tf32r(float a) {
    uint32_t r;                       // tf32 cvt needs a .b32 destination
    asm("cvt.rna.tf32.f32 %0, %1;" : "=r"(r) : "f"(a));
    return __uint_as_float(r);
}
__device__ __forceinline__ float fsqrt_ap(float x) {
    float r; asm("sqrt.approx.f32 %0, %1;" : "=f"(r) : "f"(x)); return r;
}
__device__ __forceinline__ float frsqrt_ap(float x) {
    float r; asm("rsqrt.approx.f32 %0, %1;" : "=f"(r) : "f"(x)); return r;
}
// D += A(16x8,row) * B(8x8,col)   tf32
__device__ __forceinline__ void mma8(float* d, float a0, float a1, float a2, float a3,
                                     float b0, float b1) {
    asm volatile(
        "mma.sync.aligned.m16n8k8.row.col.f32.tf32.tf32.f32 "
        "{%0,%1,%2,%3}, {%4,%5,%6,%7}, {%8,%9}, {%0,%1,%2,%3};"
        : "+f"(d[0]), "+f"(d[1]), "+f"(d[2]), "+f"(d[3])
        : "r"(__float_as_uint(a0)), "r"(__float_as_uint(a1)),
          "r"(__float_as_uint(a2)), "r"(__float_as_uint(a3)),
          "r"(__float_as_uint(b0)), "r"(__float_as_uint(b1)));
}

// ============================ main kernel ============================
__global__ __launch_bounds__(256, 1)
void main_kernel(const float* __restrict__ X, const float* __restrict__ A,
                 const float* __restrict__ C) {
    extern __shared__ float sm[];
    float* As  = sm;                 // [n][k] pad 132 (tf32)   -> later Ws [b][n]
    float* Xs  = sm + XS_OFF;        // [b][k] pad 132 (tf32)
    float* Cs  = sm + CS_OFF;        // [n][c] pad 120 (tf32), col100=1, 101..119=0
    float* x2s = sm + X2_OFF;
    float* y2s = sm + Y2_OFF;

    const int tid = threadIdx.x;
    const int w   = tid >> 5;
    const int l   = tid & 31;
    const int g   = l >> 2;          // 0..7
    const int tg  = l & 3;           // 0..3
    const int n0  = blockIdx.x * 128;

    // ---------------- load + project + transpose ----------------
#pragma unroll
    for (int it = 0; it < 16; it++) {
        const int r = it * 8 + w;
        // A row -> As[r][*], x2
        float4 va = ((const float4*)(A + (size_t)(n0 + r) * 128))[l];
        float sa = va.x * va.x + va.y * va.y + va.z * va.z + va.w * va.w;
#pragma unroll
        for (int off = 16; off > 0; off >>= 1)
            sa += __shfl_xor_sync(0xffffffffu, sa, off);
        if (l == 0) x2s[r] = sa;
        *(float4*)&As[r * PADA + l * 4] =
            make_float4(tf32r(va.x), tf32r(va.y), tf32r(va.z), tf32r(va.w));

        // X row -> project -> Xs[r][*], y2
        float4 vx = ((const float4*)(X + (size_t)r * 128))[l];
        float sx = vx.x * vx.x + vx.y * vx.y + vx.z * vx.z + vx.w * vx.w;
#pragma unroll
        for (int off = 16; off > 0; off >>= 1)
            sx += __shfl_xor_sync(0xffffffffu, sx, off);
        float norm  = fmaxf(sqrtf(sx), 1e-15f);
        const float maxn = 1.0f - 4e-3f;
        float scale = (norm > maxn) ? (maxn / norm) : 1.0f;
        if (l == 0) y2s[r] = sx * scale * scale;
        vx.x *= scale; vx.y *= scale; vx.z *= scale; vx.w *= scale;
        *(float4*)&Xs[r * PADA + l * 4] =
            make_float4(tf32r(vx.x), tf32r(vx.y), tf32r(vx.z), tf32r(vx.w));

        // C row -> Cs[r][*] (K-major for GEMM2 B), ones col at 100
        float4 vc = make_float4(0.f, 0.f, 0.f, 0.f);
        if (l < 25)      vc = ((const float4*)(C + (size_t)(n0 + r) * NCq))[l];
        else if (l == 25) vc = make_float4(1.0f, 0.f, 0.f, 0.f);
        if (l < 30)
            *(float4*)&Cs[r * PADC + l * 4] =
                make_float4(tf32r(vc.x), tf32r(vc.y), tf32r(vc.z), tf32r(vc.w));
    }
    __syncthreads();

    // ---------------- GEMM1: D1[n][b] = A @ Xp^T ----------------
    // warp tile: 32n x 64b   (wn = w>>1 in 0..3, wb = w&1)
    const int wn = w >> 1, wb = w & 1;
    const float* Ab = As + (wn * 32) * PADA;
    const float* Xb = Xs + (wb * 64) * PADA;

    float acc[2][8][4];
#pragma unroll
    for (int mt = 0; mt < 2; mt++)
#pragma unroll
        for (int bt = 0; bt < 8; bt++)
#pragma unroll
            for (int rr = 0; rr < 4; rr++) acc[mt][bt][rr] = 0.f;

#pragma unroll
    for (int ks = 0; ks < 16; ks++) {
        const int kc = ks * 8 + tg;
        float a0[2], a1[2], a2[2], a3[2];
#pragma unroll
        for (int mt = 0; mt < 2; mt++) {
            a0[mt] = Ab[(mt * 16 + g) * PADA + kc];
            a1[mt] = Ab[(mt * 16 + 8 + g) * PADA + kc];
            a2[mt] = Ab[(mt * 16 + g) * PADA + kc + 4];
            a3[mt] = Ab[(mt * 16 + 8 + g) * PADA + kc + 4];
        }
#pragma unroll
        for (int bt = 0; bt < 8; bt++) {
            float b0 = Xb[(bt * 8 + g) * PADA + kc];
            float b1 = Xb[(bt * 8 + g) * PADA + kc + 4];
            mma8(acc[0][bt], a0[0], a1[0], a2[0], a3[0], b0, b1);
            mma8(acc[1][bt], a0[1], a1[1], a2[1], a3[1], b0, b1);
        }
    }

    // ---------------- epilogue: dot -> w (in-place in acc) ----------------
    // w = (PxPy)^(1/4) * rsqrt(sqrt(den) + sqrt(||x-y||^2))
    float x2v[4], px4[4];
#pragma unroll
    for (int mt = 0; mt < 2; mt++)
#pragma unroll
        for (int h = 0; h < 2; h++) {
            float x2 = x2s[wn * 32 + mt * 16 + h * 8 + g];
            x2v[mt * 2 + h] = x2;
            px4[mt * 2 + h] = fsqrt_ap(fsqrt_ap(1.0f - x2));
        }
    float y2v[16], py4[16];
#pragma unroll
    for (int bt = 0; bt < 8; bt++)
#pragma unroll
        for (int j = 0; j < 2; j++) {
            float y2 = y2s[wb * 64 + bt * 8 + 2 * tg + j];
            y2v[bt * 2 + j] = y2;
            py4[bt * 2 + j] = fsqrt_ap(fsqrt_ap(1.0f - y2));
        }
#pragma unroll
    for (int mt = 0; mt < 2; mt++)
#pragma unroll
        for (int bt = 0; bt < 8; bt++)
#pragma unroll
            for (int rr = 0; rr < 4; rr++) {
                const int hi = rr >> 1, j = rr & 1;
                float dot = acc[mt][bt][rr];
                float x2  = x2v[mt * 2 + hi];
                float y2  = y2v[bt * 2 + j];
                float den = fmaf(x2, y2, fmaf(-2.0f, dot, 1.0f));
                float v2  = fmaxf(fmaf(-2.0f, dot, x2 + y2), 0.0f);
                float s   = fsqrt_ap(den) + fsqrt_ap(v2);
                float wq  = px4[mt * 2 + hi] * py4[bt * 2 + j] * frsqrt_ap(s);
                wq = fminf(fmaxf(wq, 0.015625f), 1.0f);   // z<=1-1e-7 clip / w<=1
                acc[mt][bt][rr] = tf32r(wq);
            }

    __syncthreads();   // all GEMM1 smem reads done before Ws overwrites As

    // store W transposed: Ws[b][n]  (alias of As)
    float* Ws = As;
#pragma unroll
    for (int mt = 0; mt < 2; mt++)
#pragma unroll
        for (int bt = 0; bt < 8; bt++) {
            const int nn = wn * 32 + mt * 16 + g;
            const int bb = wb * 64 + bt * 8 + 2 * tg;
            Ws[(bb)     * PADA + nn]     = acc[mt][bt][0];
            Ws[(bb + 1) * PADA + nn]     = acc[mt][bt][1];
            Ws[(bb)     * PADA + nn + 8] = acc[mt][bt][2];
            Ws[(bb + 1) * PADA + nn + 8] = acc[mt][bt][3];
        }
    __syncthreads();

    // ---------------- GEMM2: O[b][c] = W @ C  (N=112, col100 = S) ----------------
    // warp tile: 32b x 56c   (wb2 = w>>1, wc = w&1)
    const int wb2 = w >> 1, wc = w & 1;
    const float* Wb = Ws + (wb2 * 32) * PADA;

    float acc2[2][7][4];
#pragma unroll
    for (int mt = 0; mt < 2; mt++)
#pragma unroll
        for (int ct = 0; ct < 7; ct++)
#pragma unroll
            for (int rr = 0; rr < 4; rr++) acc2[mt][ct][rr] = 0.f;

#pragma unroll
    for (int ks = 0; ks < 16; ks++) {
        const int kc = ks * 8 + tg;
        float a0[2], a1[2], a2[2], a3[2];
#pragma unroll
        for (int mt = 0; mt < 2; mt++) {
            a0[mt] = Wb[(mt * 16 + g) * PADA + kc];
            a1[mt] = Wb[(mt * 16 + 8 + g) * PADA + kc];
            a2[mt] = Wb[(mt * 16 + g) * PADA + kc + 4];
            a3[mt] = Wb[(mt * 16 + 8 + g) * PADA + kc + 4];
        }
#pragma unroll
        for (int ct = 0; ct < 7; ct++) {
            const int col = wc * 56 + ct * 8 + g;
            float b0 = Cs[(kc)     * PADC + col];
            float b1 = Cs[(kc + 4) * PADC + col];
            mma8(acc2[0][ct], a0[0], a1[0], a2[0], a3[0], b0, b1);
            mma8(acc2[1][ct], a0[1], a1[1], a2[1], a3[1], b0, b1);
        }
    }

    // ---------------- store partials ----------------
    const size_t obase = (size_t)blockIdx.x * 128;
#pragma unroll
    for (int mt = 0; mt < 2; mt++)
#pragma unroll
        for (int ct = 0; ct < 7; ct++) {
            const int c = wc * 56 + ct * 8 + 2 * tg;
            const int b = wb2 * 32 + mt * 16 + g;
            if (c < NCq) {
                *(float2*)&g_Opart[(obase + b) * NCq + c] =
                    make_float2(acc2[mt][ct][0], acc2[mt][ct][1]);
                *(float2*)&g_Opart[(obase + b + 8) * NCq + c] =
                    make_float2(acc2[mt][ct][2], acc2[mt][ct][3]);
            } else if (c == NCq) {   // ones column -> softmax denominator
                g_Spart[obase + b]     = acc2[mt][ct][0];
                g_Spart[obase + b + 8] = acc2[mt][ct][2];
            }
        }
}

// ============================ reduction ============================
// One block per batch row b. 512 threads = 4 kb-splits x 128 c-lanes.
// o-loads are fully coalesced 400B rows; unroll-8 gives ~8 L2 loads in flight.
__global__ __launch_bounds__(512)
void reduce_kernel(float* __restrict__ out) {
    __shared__ float so[4][128];
    __shared__ float ssum[4];

    const int b     = blockIdx.x;
    const int tid   = threadIdx.x;
    const int split = tid >> 7;      // 0..3
    const int c     = tid & 127;

    float o = 0.f, s = 0.f;
    const int kb0 = split * 32;
#pragma unroll 8
    for (int i = 0; i < 32; i++) {
        const int kb = kb0 + i;
        s += g_Spart[kb * 128 + b];                       // broadcast load
        if (c < NCq)
            o += g_Opart[(size_t)(kb * 128 + b) * NCq + c];  // coalesced row
    }
    so[split][c] = o;
    if (c == 0) ssum[split] = s;
    __syncthreads();

    if (split == 0 && c < NCq) {
        float ot = so[0][c] + so[1][c] + so[2][c] + so[3][c];
        float st = ssum[0] + ssum[1] + ssum[2] + ssum[3];
        out[b * NCq + c] = ot / st;
    }
}

// ============================ launch ============================
extern "C" void kernel_launch(void* const* d_in, const int* in_sizes, int n_in,
                              void* d_out, int out_size) {
    (void)in_sizes; (void)n_in; (void)out_size;
    const float* X = (const float*)d_in[0];   // [128,128]
    const float* A = (const float*)d_in[1];   // [16384,1,128]
    const float* C = (const float*)d_in[2];   // [16384,100]
    float* out = (float*)d_out;               // [128,100] fp32

    cudaFuncSetAttribute(main_kernel,
                         cudaFuncAttributeMaxDynamicSharedMemorySize, SMEM_BYTES);

    main_kernel<<<NBLKS, 256, SMEM_BYTES>>>(X, A, C);
    reduce_kernel<<<128, 512>>>(out);
}

// round 6
// speedup vs baseline: 2.5076x; 1.0854x over previous
#include <cuda_runtime.h>
#include <cuda_fp16.h>
#include <cstdint>

#define NCq   100
#define NCPAD 104
#define NBLKS 128
#define PADA  132      /* Ws row stride (floats) */
#define PADC  120      /* Cs row stride (floats) */
#define PADH  136      /* Ah / Xh row stride (halves) */

// ---- static device scratch (no allocations allowed) ----
__device__ float g_Spart[128 * NBLKS];            // [b][kb]
__device__ float g_Opart[128 * NBLKS * NCPAD];    // [b][kb][104], pads stay 0

// smem layout (bytes)
#define XH_OFFB  (128 * PADH * 2)                 /* 34816  */
#define CS_OFFB  (2 * 128 * PADH * 2)             /* 69632  */
#define X2_OFFB  (CS_OFFB + 128 * PADC * 4)       /* 131072 */
#define Y2_OFFB  (X2_OFFB + 512)
#define SMEM_BYTES (Y2_OFFB + 512)                /* 132096 */

// ============================ helpers ============================
__device__ __forceinline__ float tf32r(float a) {
    uint32_t r;
    asm("cvt.rna.tf32.f32 %0, %1;" : "=r"(r) : "f"(a));
    return __uint_as_float(r);
}
__device__ __forceinline__ float fsqrt_ap(float x) {
    float r; asm("sqrt.approx.f32 %0, %1;" : "=f"(r) : "f"(x)); return r;
}
__device__ __forceinline__ float frsqrt_ap(float x) {
    float r; asm("rsqrt.approx.f32 %0, %1;" : "=f"(r) : "f"(x)); return r;
}
__device__ __forceinline__ uint2 pack4h(float4 v) {
    __half2 h01 = __floats2half2_rn(v.x, v.y);
    __half2 h23 = __floats2half2_rn(v.z, v.w);
    uint2 u;
    u.x = *(uint32_t*)&h01;
    u.y = *(uint32_t*)&h23;
    return u;
}
// fp16 m16n8k16: D(f32) += A(f16) * B(f16)
__device__ __forceinline__ void mma16(float* d, uint32_t a0, uint32_t a1,
                                      uint32_t a2, uint32_t a3,
                                      uint32_t b0, uint32_t b1) {
    asm volatile(
        "mma.sync.aligned.m16n8k16.row.col.f32.f16.f16.f32 "
        "{%0,%1,%2,%3}, {%4,%5,%6,%7}, {%8,%9}, {%0,%1,%2,%3};"
        : "+f"(d[0]), "+f"(d[1]), "+f"(d[2]), "+f"(d[3])
        : "r"(a0), "r"(a1), "r"(a2), "r"(a3), "r"(b0), "r"(b1));
}
// tf32 m16n8k8
__device__ __forceinline__ void mma8(float* d, float a0, float a1, float a2, float a3,
                                     float b0, float b1) {
    asm volatile(
        "mma.sync.aligned.m16n8k8.row.col.f32.tf32.tf32.f32 "
        "{%0,%1,%2,%3}, {%4,%5,%6,%7}, {%8,%9}, {%0,%1,%2,%3};"
        : "+f"(d[0]), "+f"(d[1]), "+f"(d[2]), "+f"(d[3])
        : "r"(__float_as_uint(a0)), "r"(__float_as_uint(a1)),
          "r"(__float_as_uint(a2)), "r"(__float_as_uint(a3)),
          "r"(__float_as_uint(b0)), "r"(__float_as_uint(b1)));
}

// ============================ main kernel ============================
__global__ __launch_bounds__(256, 1)
void main_kernel(const float* __restrict__ X, const float* __restrict__ A,
                 const float* __restrict__ C) {
    extern __shared__ __align__(16) char smb[];
    __half* Ah  = (__half*)smb;                   // [n][k] fp16, stride PADH
    __half* Xh  = (__half*)(smb + XH_OFFB);       // [b][k] fp16, stride PADH
    float*  Cs  = (float*)(smb + CS_OFFB);        // [n][c] tf32, stride PADC
    float*  x2s = (float*)(smb + X2_OFFB);
    float*  y2s = (float*)(smb + Y2_OFFB);
    float*  Ws  = (float*)smb;                    // later: [b][n] f32, stride PADA
                                                  // (aliases Ah+Xh = 69632B >= 67584B)
    const int tid = threadIdx.x;
    const int w   = tid >> 5;
    const int l   = tid & 31;
    const int g   = l >> 2;          // 0..7
    const int tg  = l & 3;           // 0..3
    const int n0  = blockIdx.x * 128;

    // ---------------- load + project + convert ----------------
#pragma unroll
    for (int it = 0; it < 16; it++) {
        const int r = it * 8 + w;
        // A row -> Ah[r][*] (fp16), x2
        float4 va = ((const float4*)(A + (size_t)(n0 + r) * 128))[l];
        float sa = va.x * va.x + va.y * va.y + va.z * va.z + va.w * va.w;
#pragma unroll
        for (int off = 16; off > 0; off >>= 1)
            sa += __shfl_xor_sync(0xffffffffu, sa, off);
        if (l == 0) x2s[r] = sa;
        *(uint2*)&Ah[r * PADH + l * 4] = pack4h(va);

        // X row -> project -> Xh[r][*] (fp16), y2
        float4 vx = ((const float4*)(X + (size_t)r * 128))[l];
        float sx = vx.x * vx.x + vx.y * vx.y + vx.z * vx.z + vx.w * vx.w;
#pragma unroll
        for (int off = 16; off > 0; off >>= 1)
            sx += __shfl_xor_sync(0xffffffffu, sx, off);
        float norm  = fmaxf(sqrtf(sx), 1e-15f);
        const float maxn = 1.0f - 4e-3f;
        float scale = (norm > maxn) ? (maxn / norm) : 1.0f;
        if (l == 0) y2s[r] = sx * scale * scale;
        vx.x *= scale; vx.y *= scale; vx.z *= scale; vx.w *= scale;
        *(uint2*)&Xh[r * PADH + l * 4] = pack4h(vx);

        // C row -> Cs[r][*] (tf32, K-major for GEMM2 B), ones col at 100
        float4 vc = make_float4(0.f, 0.f, 0.f, 0.f);
        if (l < 25)       vc = ((const float4*)(C + (size_t)(n0 + r) * NCq))[l];
        else if (l == 25) vc = make_float4(1.0f, 0.f, 0.f, 0.f);
        if (l < 30)
            *(float4*)&Cs[r * PADC + l * 4] =
                make_float4(tf32r(vc.x), tf32r(vc.y), tf32r(vc.z), tf32r(vc.w));
    }
    __syncthreads();

    // ---------------- GEMM1 (fp16): D1[n][b] = A @ Xp^T ----------------
    // warp tile: 32n x 64b   (wn = w>>1, wb = w&1)
    const int wn = w >> 1, wb = w & 1;
    const __half* Abh = Ah + (wn * 32) * PADH;
    const __half* Xbh = Xh + (wb * 64) * PADH;

    float acc[2][8][4];
#pragma unroll
    for (int mt = 0; mt < 2; mt++)
#pragma unroll
        for (int bt = 0; bt < 8; bt++)
#pragma unroll
            for (int rr = 0; rr < 4; rr++) acc[mt][bt][rr] = 0.f;

#pragma unroll
    for (int ks = 0; ks < 8; ks++) {
        const int k0 = ks * 16 + 2 * tg;
        uint32_t a0[2], a1[2], a2[2], a3[2];
#pragma unroll
        for (int mt = 0; mt < 2; mt++) {
            a0[mt] = *(const uint32_t*)&Abh[(mt * 16 + g)     * PADH + k0];
            a1[mt] = *(const uint32_t*)&Abh[(mt * 16 + 8 + g) * PADH + k0];
            a2[mt] = *(const uint32_t*)&Abh[(mt * 16 + g)     * PADH + k0 + 8];
            a3[mt] = *(const uint32_t*)&Abh[(mt * 16 + 8 + g) * PADH + k0 + 8];
        }
#pragma unroll
        for (int bt = 0; bt < 8; bt++) {
            uint32_t b0 = *(const uint32_t*)&Xbh[(bt * 8 + g) * PADH + k0];
            uint32_t b1 = *(const uint32_t*)&Xbh[(bt * 8 + g) * PADH + k0 + 8];
            mma16(acc[0][bt], a0[0], a1[0], a2[0], a3[0], b0, b1);
            mma16(acc[1][bt], a0[1], a1[1], a2[1], a3[1], b0, b1);
        }
    }

    // ---------------- epilogue: dot -> w ----------------
    // w = (PxPy)^(1/4) * rsqrt(sqrt(den) + sqrt(||x-y||^2))
    float x2v[4], px4[4];
#pragma unroll
    for (int mt = 0; mt < 2; mt++)
#pragma unroll
        for (int h = 0; h < 2; h++) {
            float x2 = x2s[wn * 32 + mt * 16 + h * 8 + g];
            x2v[mt * 2 + h] = x2;
            px4[mt * 2 + h] = fsqrt_ap(fsqrt_ap(1.0f - x2));
        }
    float y2v[16], py4[16];
#pragma unroll
    for (int bt = 0; bt < 8; bt++)
#pragma unroll
        for (int j = 0; j < 2; j++) {
            float y2 = y2s[wb * 64 + bt * 8 + 2 * tg + j];
            y2v[bt * 2 + j] = y2;
            py4[bt * 2 + j] = fsqrt_ap(fsqrt_ap(1.0f - y2));
        }
#pragma unroll
    for (int mt = 0; mt < 2; mt++)
#pragma unroll
        for (int bt = 0; bt < 8; bt++)
#pragma unroll
            for (int rr = 0; rr < 4; rr++) {
                const int hi = rr >> 1, j = rr & 1;
                float dot = acc[mt][bt][rr];
                float x2  = x2v[mt * 2 + hi];
                float y2  = y2v[bt * 2 + j];
                float den = fmaf(x2, y2, fmaf(-2.0f, dot, 1.0f));
                float v2  = fmaxf(fmaf(-2.0f, dot, x2 + y2), 0.0f);
                float s   = fsqrt_ap(den) + fsqrt_ap(v2);
                float wq  = px4[mt * 2 + hi] * py4[bt * 2 + j] * frsqrt_ap(s);
                wq = fminf(fmaxf(wq, 0.015625f), 1.0f);
                acc[mt][bt][rr] = tf32r(wq);
            }

    __syncthreads();   // all GEMM1 smem reads done before Ws overwrites Ah/Xh

    // store W transposed: Ws[b][n] (f32, aliases Ah/Xh region)
#pragma unroll
    for (int mt = 0; mt < 2; mt++)
#pragma unroll
        for (int bt = 0; bt < 8; bt++) {
            const int nn = wn * 32 + mt * 16 + g;
            const int bb = wb * 64 + bt * 8 + 2 * tg;
            Ws[(bb)     * PADA + nn]     = acc[mt][bt][0];
            Ws[(bb + 1) * PADA + nn]     = acc[mt][bt][1];
            Ws[(bb)     * PADA + nn + 8] = acc[mt][bt][2];
            Ws[(bb + 1) * PADA + nn + 8] = acc[mt][bt][3];
        }
    __syncthreads();

    // ---------------- GEMM2 (tf32): O[b][c] = W @ C  (N=112, col100 = S) ----------------
    const int wb2 = w >> 1, wc = w & 1;
    const float* Wb = Ws + (wb2 * 32) * PADA;

    float acc2[2][7][4];
#pragma unroll
    for (int mt = 0; mt < 2; mt++)
#pragma unroll
        for (int ct = 0; ct < 7; ct++)
#pragma unroll
            for (int rr = 0; rr < 4; rr++) acc2[mt][ct][rr] = 0.f;

#pragma unroll
    for (int ks = 0; ks < 16; ks++) {
        const int kc = ks * 8 + tg;
        float a0[2], a1[2], a2[2], a3[2];
#pragma unroll
        for (int mt = 0; mt < 2; mt++) {
            a0[mt] = Wb[(mt * 16 + g)     * PADA + kc];
            a1[mt] = Wb[(mt * 16 + 8 + g) * PADA + kc];
            a2[mt] = Wb[(mt * 16 + g)     * PADA + kc + 4];
            a3[mt] = Wb[(mt * 16 + 8 + g) * PADA + kc + 4];
        }
#pragma unroll
        for (int ct = 0; ct < 7; ct++) {
            const int col = wc * 56 + ct * 8 + g;
            float b0 = Cs[(kc)     * PADC + col];
            float b1 = Cs[(kc + 4) * PADC + col];
            mma8(acc2[0][ct], a0[0], a1[0], a2[0], a3[0], b0, b1);
            mma8(acc2[1][ct], a0[1], a1[1], a2[1], a3[1], b0, b1);
        }
    }

    // ---------------- store partials: Opart[b][kb][104], Spart[b][kb] ----------------
    const int kb = blockIdx.x;
#pragma unroll
    for (int mt = 0; mt < 2; mt++)
#pragma unroll
        for (int ct = 0; ct < 7; ct++) {
            const int c = wc * 56 + ct * 8 + 2 * tg;
            const int b = wb2 * 32 + mt * 16 + g;
            if (c < NCq) {
                *(float2*)&g_Opart[((size_t)b * NBLKS + kb) * NCPAD + c] =
                    make_float2(acc2[mt][ct][0], acc2[mt][ct][1]);
                *(float2*)&g_Opart[((size_t)(b + 8) * NBLKS + kb) * NCPAD + c] =
                    make_float2(acc2[mt][ct][2], acc2[mt][ct][3]);
            } else if (c == NCq) {   // ones column -> softmax denominator
                g_Spart[b * NBLKS + kb]       = acc2[mt][ct][0];
                g_Spart[(b + 8) * NBLKS + kb] = acc2[mt][ct][2];
            }
        }
}

// ============================ reduction ============================
// Block b: contiguous 53KB region Opart[b]. 4 kb-splits x 128 c-lanes,
// 4 independent accumulators -> 32 loads in flight per thread.
__global__ __launch_bounds__(512)
void reduce_kernel(float* __restrict__ out) {
    __shared__ float so[4][NCPAD];
    __shared__ float ssum[4];

    const int b     = blockIdx.x;
    const int tid   = threadIdx.x;
    const int split = tid >> 7;      // 0..3
    const int c     = tid & 127;

    float o0 = 0.f, o1 = 0.f, o2 = 0.f, o3 = 0.f;
    if (c < NCPAD) {
        const float* ob = g_Opart + ((size_t)b * NBLKS + split * 32) * NCPAD + c;
#pragma unroll
        for (int i = 0; i < 32; i += 4) {
            o0 += ob[(i + 0) * NCPAD];
            o1 += ob[(i + 1) * NCPAD];
            o2 += ob[(i + 2) * NCPAD];
            o3 += ob[(i + 3) * NCPAD];
        }
    }
    float s0 = 0.f, s1 = 0.f, s2 = 0.f, s3 = 0.f;
    {
        const float* sb = g_Spart + b * NBLKS + split * 32;
#pragma unroll
        for (int i = 0; i < 32; i += 4) {
            s0 += sb[i + 0]; s1 += sb[i + 1]; s2 += sb[i + 2]; s3 += sb[i + 3];
        }
    }
    if (c < NCPAD) so[split][c] = (o0 + o1) + (o2 + o3);
    if (c == 0)    ssum[split]  = (s0 + s1) + (s2 + s3);
    __syncthreads();

    if (split == 0 && c < NCq) {
        float ot = (so[0][c] + so[1][c]) + (so[2][c] + so[3][c]);
        float st = (ssum[0] + ssum[1]) + (ssum[2] + ssum[3]);
        out[b * NCq + c] = ot / st;
    }
}

// ============================ launch ============================
extern "C" void kernel_launch(void* const* d_in, const int* in_sizes, int n_in,
                              void* d_out, int out_size) {
    (void)in_sizes; (void)n_in; (void)out_size;
    const float* X = (const float*)d_in[0];   // [128,128]
    const float* A = (const float*)d_in[1];   // [16384,1,128]
    const float* C = (const float*)d_in[2];   // [16384,100]
    float* out = (float*)d_out;               // [128,100] fp32

    cudaFuncSetAttribute(main_kernel,
                         cudaFuncAttributeMaxDynamicSharedMemorySize, SMEM_BYTES);

    main_kernel<<<NBLKS, 256, SMEM_BYTES>>>(X, A, C);
    reduce_kernel<<<128, 512>>>(out);
}

// round 7
// speedup vs baseline: 2.9654x; 1.1826x over previous
#include <cuda_runtime.h>
#include <cuda_fp16.h>
#include <cstdint>

#define NCq   100
#define NCPAD 104
#define NBLKS 128
#define PADA  132      /* Ws row stride (floats) */
#define PADC  120      /* Cs row stride (floats) */
#define PADH  136      /* Ah / Xh row stride (halves) */

// ---- static device scratch (no allocations allowed) ----
__device__ float g_Spart[128 * NBLKS];            // [b][kb]
__device__ float g_Opart[128 * NBLKS * NCPAD];    // [b][kb][104], pads stay 0

// smem layout (bytes)
#define XH_OFFB  (128 * PADH * 2)                 /* 34816  */
#define CS_OFFB  (2 * 128 * PADH * 2)             /* 69632  */
#define X2_OFFB  (CS_OFFB + 128 * PADC * 4)       /* 131072 */
#define Y2_OFFB  (X2_OFFB + 512)
#define SMEM_BYTES (Y2_OFFB + 512)                /* 132096 */

// ============================ helpers ============================
__device__ __forceinline__ float tf32r(float a) {
    uint32_t r;
    asm("cvt.rna.tf32.f32 %0, %1;" : "=r"(r) : "f"(a));
    return __uint_as_float(r);
}
__device__ __forceinline__ float fsqrt_ap(float x) {
    float r; asm("sqrt.approx.f32 %0, %1;" : "=f"(r) : "f"(x)); return r;
}
__device__ __forceinline__ float frsqrt_ap(float x) {
    float r; asm("rsqrt.approx.f32 %0, %1;" : "=f"(r) : "f"(x)); return r;
}
__device__ __forceinline__ uint2 pack4h(float4 v) {
    __half2 h01 = __floats2half2_rn(v.x, v.y);
    __half2 h23 = __floats2half2_rn(v.z, v.w);
    uint2 u;
    u.x = *(uint32_t*)&h01;
    u.y = *(uint32_t*)&h23;
    return u;
}
// fp16 m16n8k16: D(f32) += A(f16) * B(f16)
__device__ __forceinline__ void mma16(float* d, uint32_t a0, uint32_t a1,
                                      uint32_t a2, uint32_t a3,
                                      uint32_t b0, uint32_t b1) {
    asm volatile(
        "mma.sync.aligned.m16n8k16.row.col.f32.f16.f16.f32 "
        "{%0,%1,%2,%3}, {%4,%5,%6,%7}, {%8,%9}, {%0,%1,%2,%3};"
        : "+f"(d[0]), "+f"(d[1]), "+f"(d[2]), "+f"(d[3])
        : "r"(a0), "r"(a1), "r"(a2), "r"(a3), "r"(b0), "r"(b1));
}
// tf32 m16n8k8
__device__ __forceinline__ void mma8(float* d, float a0, float a1, float a2, float a3,
                                     float b0, float b1) {
    asm volatile(
        "mma.sync.aligned.m16n8k8.row.col.f32.tf32.tf32.f32 "
        "{%0,%1,%2,%3}, {%4,%5,%6,%7}, {%8,%9}, {%0,%1,%2,%3};"
        : "+f"(d[0]), "+f"(d[1]), "+f"(d[2]), "+f"(d[3])
        : "r"(__float_as_uint(a0)), "r"(__float_as_uint(a1)),
          "r"(__float_as_uint(a2)), "r"(__float_as_uint(a3)),
          "r"(__float_as_uint(b0)), "r"(__float_as_uint(b1)));
}

// ============================ main kernel ============================
__global__ __launch_bounds__(512, 1)
void main_kernel(const float* __restrict__ X, const float* __restrict__ A,
                 const float* __restrict__ C) {
    extern __shared__ __align__(16) char smb[];
    __half* Ah  = (__half*)smb;                   // [n][k] fp16, stride PADH
    __half* Xh  = (__half*)(smb + XH_OFFB);       // [b][k] fp16, stride PADH
    float*  Cs  = (float*)(smb + CS_OFFB);        // [n][c] tf32, stride PADC
    float*  x2s = (float*)(smb + X2_OFFB);
    float*  y2s = (float*)(smb + Y2_OFFB);
    float*  Ws  = (float*)smb;                    // later: [b][n] f32, stride PADA
                                                  // (aliases Ah+Xh = 69632B >= 67584B)
    const int tid = threadIdx.x;
    const int w   = tid >> 5;        // 0..15
    const int l   = tid & 31;
    const int g   = l >> 2;          // 0..7
    const int tg  = l & 3;           // 0..3
    const int n0  = blockIdx.x * 128;

    // ---------------- load + project + convert (8 iters, 16 rows/iter) ----------------
#pragma unroll
    for (int it = 0; it < 8; it++) {
        const int r = it * 16 + w;
        // A row -> Ah[r][*] (fp16), x2
        float4 va = ((const float4*)(A + (size_t)(n0 + r) * 128))[l];
        float sa = va.x * va.x + va.y * va.y + va.z * va.z + va.w * va.w;
#pragma unroll
        for (int off = 16; off > 0; off >>= 1)
            sa += __shfl_xor_sync(0xffffffffu, sa, off);
        if (l == 0) x2s[r] = sa;
        *(uint2*)&Ah[r * PADH + l * 4] = pack4h(va);

        // X row -> project -> Xh[r][*] (fp16), y2
        float4 vx = ((const float4*)(X + (size_t)r * 128))[l];
        float sx = vx.x * vx.x + vx.y * vx.y + vx.z * vx.z + vx.w * vx.w;
#pragma unroll
        for (int off = 16; off > 0; off >>= 1)
            sx += __shfl_xor_sync(0xffffffffu, sx, off);
        float norm  = fmaxf(sqrtf(sx), 1e-15f);
        const float maxn = 1.0f - 4e-3f;
        float scale = (norm > maxn) ? (maxn / norm) : 1.0f;
        if (l == 0) y2s[r] = sx * scale * scale;
        vx.x *= scale; vx.y *= scale; vx.z *= scale; vx.w *= scale;
        *(uint2*)&Xh[r * PADH + l * 4] = pack4h(vx);

        // C row -> Cs[r][*] (tf32, K-major for GEMM2 B), ones col at 100
        float4 vc = make_float4(0.f, 0.f, 0.f, 0.f);
        if (l < 25)       vc = ((const float4*)(C + (size_t)(n0 + r) * NCq))[l];
        else if (l == 25) vc = make_float4(1.0f, 0.f, 0.f, 0.f);
        if (l < 30)
            *(float4*)&Cs[r * PADC + l * 4] =
                make_float4(tf32r(vc.x), tf32r(vc.y), tf32r(vc.z), tf32r(vc.w));
    }
    __syncthreads();

    // ---------------- GEMM1 (fp16): D1[n][b] = A @ Xp^T ----------------
    // 16 warps in 4x4 grid: each warp 32n x 32b
    const int wn = w >> 2, wb = w & 3;
    const __half* Abh = Ah + (wn * 32) * PADH;
    const __half* Xbh = Xh + (wb * 32) * PADH;

    float acc[2][4][4];
#pragma unroll
    for (int mt = 0; mt < 2; mt++)
#pragma unroll
        for (int bt = 0; bt < 4; bt++)
#pragma unroll
            for (int rr = 0; rr < 4; rr++) acc[mt][bt][rr] = 0.f;

#pragma unroll
    for (int ks = 0; ks < 8; ks++) {
        const int k0 = ks * 16 + 2 * tg;
        uint32_t a0[2], a1[2], a2[2], a3[2];
#pragma unroll
        for (int mt = 0; mt < 2; mt++) {
            a0[mt] = *(const uint32_t*)&Abh[(mt * 16 + g)     * PADH + k0];
            a1[mt] = *(const uint32_t*)&Abh[(mt * 16 + 8 + g) * PADH + k0];
            a2[mt] = *(const uint32_t*)&Abh[(mt * 16 + g)     * PADH + k0 + 8];
            a3[mt] = *(const uint32_t*)&Abh[(mt * 16 + 8 + g) * PADH + k0 + 8];
        }
#pragma unroll
        for (int bt = 0; bt < 4; bt++) {
            uint32_t b0 = *(const uint32_t*)&Xbh[(bt * 8 + g) * PADH + k0];
            uint32_t b1 = *(const uint32_t*)&Xbh[(bt * 8 + g) * PADH + k0 + 8];
            mma16(acc[0][bt], a0[0], a1[0], a2[0], a3[0], b0, b1);
            mma16(acc[1][bt], a0[1], a1[1], a2[1], a3[1], b0, b1);
        }
    }

    // ---------------- epilogue: dot -> w ----------------
    // w = (PxPy)^(1/4) * rsqrt(sqrt(den) + sqrt(||x-y||^2))
    float x2v[4], px4[4];
#pragma unroll
    for (int mt = 0; mt < 2; mt++)
#pragma unroll
        for (int h = 0; h < 2; h++) {
            float x2 = x2s[wn * 32 + mt * 16 + h * 8 + g];
            x2v[mt * 2 + h] = x2;
            px4[mt * 2 + h] = fsqrt_ap(fsqrt_ap(1.0f - x2));
        }
    float y2v[8], py4[8];
#pragma unroll
    for (int bt = 0; bt < 4; bt++)
#pragma unroll
        for (int j = 0; j < 2; j++) {
            float y2 = y2s[wb * 32 + bt * 8 + 2 * tg + j];
            y2v[bt * 2 + j] = y2;
            py4[bt * 2 + j] = fsqrt_ap(fsqrt_ap(1.0f - y2));
        }
#pragma unroll
    for (int mt = 0; mt < 2; mt++)
#pragma unroll
        for (int bt = 0; bt < 4; bt++)
#pragma unroll
            for (int rr = 0; rr < 4; rr++) {
                const int hi = rr >> 1, j = rr & 1;
                float dot = acc[mt][bt][rr];
                float x2  = x2v[mt * 2 + hi];
                float y2  = y2v[bt * 2 + j];
                float den = fmaf(x2, y2, fmaf(-2.0f, dot, 1.0f));
                float v2  = fmaxf(fmaf(-2.0f, dot, x2 + y2), 0.0f);
                float s   = fsqrt_ap(den) + fsqrt_ap(v2);
                float wq  = px4[mt * 2 + hi] * py4[bt * 2 + j] * frsqrt_ap(s);
                wq = fminf(fmaxf(wq, 0.015625f), 1.0f);
                acc[mt][bt][rr] = tf32r(wq);
            }

    __syncthreads();   // all GEMM1 smem reads done before Ws overwrites Ah/Xh

    // store W transposed: Ws[b][n] (f32, aliases Ah/Xh region)
#pragma unroll
    for (int mt = 0; mt < 2; mt++)
#pragma unroll
        for (int bt = 0; bt < 4; bt++) {
            const int nn = wn * 32 + mt * 16 + g;
            const int bb = wb * 32 + bt * 8 + 2 * tg;
            Ws[(bb)     * PADA + nn]     = acc[mt][bt][0];
            Ws[(bb + 1) * PADA + nn]     = acc[mt][bt][1];
            Ws[(bb)     * PADA + nn + 8] = acc[mt][bt][2];
            Ws[(bb + 1) * PADA + nn + 8] = acc[mt][bt][3];
        }
    __syncthreads();

    // ---------------- GEMM2 (tf32): O[b][c] = W @ C  (N=112, col100 = S) ----------------
    // 16 warps in 8x2 grid: each warp 16b x 56c
    const int wb2 = w >> 1, wc = w & 1;
    const float* Wb = Ws + (wb2 * 16) * PADA;

    float acc2[7][4];
#pragma unroll
    for (int ct = 0; ct < 7; ct++)
#pragma unroll
        for (int rr = 0; rr < 4; rr++) acc2[ct][rr] = 0.f;

#pragma unroll
    for (int ks = 0; ks < 16; ks++) {
        const int kc = ks * 8 + tg;
        float a0 = Wb[(g)     * PADA + kc];
        float a1 = Wb[(8 + g) * PADA + kc];
        float a2 = Wb[(g)     * PADA + kc + 4];
        float a3 = Wb[(8 + g) * PADA + kc + 4];
#pragma unroll
        for (int ct = 0; ct < 7; ct++) {
            const int col = wc * 56 + ct * 8 + g;
            float b0 = Cs[(kc)     * PADC + col];
            float b1 = Cs[(kc + 4) * PADC + col];
            mma8(acc2[ct], a0, a1, a2, a3, b0, b1);
        }
    }

    // ---------------- store partials: Opart[b][kb][104], Spart[b][kb] ----------------
    const int kb = blockIdx.x;
#pragma unroll
    for (int ct = 0; ct < 7; ct++) {
        const int c = wc * 56 + ct * 8 + 2 * tg;
        const int b = wb2 * 16 + g;
        if (c < NCq) {
            *(float2*)&g_Opart[((size_t)b * NBLKS + kb) * NCPAD + c] =
                make_float2(acc2[ct][0], acc2[ct][1]);
            *(float2*)&g_Opart[((size_t)(b + 8) * NBLKS + kb) * NCPAD + c] =
                make_float2(acc2[ct][2], acc2[ct][3]);
        } else if (c == NCq) {   // ones column -> softmax denominator
            g_Spart[b * NBLKS + kb]       = acc2[ct][0];
            g_Spart[(b + 8) * NBLKS + kb] = acc2[ct][2];
        }
    }
}

// ============================ reduction ============================
// Block b: 512 threads = 8 kb-splits x 64 float2-lanes over Opart[b][*][104].
// 16 float2 loads/thread into 4 independent accumulators.
__global__ __launch_bounds__(512)
void reduce_kernel(float* __restrict__ out) {
    __shared__ float2 so[8][52];
    __shared__ float  ssum[8];

    const int b     = blockIdx.x;
    const int tid   = threadIdx.x;
    const int split = tid >> 6;      // 0..7
    const int lane  = tid & 63;      // float2 lane: c = 2*lane

    float2 o0 = {0.f, 0.f}, o1 = {0.f, 0.f}, o2 = {0.f, 0.f}, o3 = {0.f, 0.f};
    if (lane < 52) {
        const float2* ob =
            (const float2*)(g_Opart + ((size_t)b * NBLKS + split * 16) * NCPAD) + lane;
#pragma unroll
        for (int i = 0; i < 16; i += 4) {
            float2 v0 = ob[(i + 0) * (NCPAD / 2)];
            float2 v1 = ob[(i + 1) * (NCPAD / 2)];
            float2 v2 = ob[(i + 2) * (NCPAD / 2)];
            float2 v3 = ob[(i + 3) * (NCPAD / 2)];
            o0.x += v0.x; o0.y += v0.y;
            o1.x += v1.x; o1.y += v1.y;
            o2.x += v2.x; o2.y += v2.y;
            o3.x += v3.x; o3.y += v3.y;
        }
        float2 t;
        t.x = (o0.x + o1.x) + (o2.x + o3.x);
        t.y = (o0.y + o1.y) + (o2.y + o3.y);
        so[split][lane] = t;
    }
    if (lane == 0) {
        const float* sb = g_Spart + b * NBLKS + split * 16;
        float s0 = 0.f, s1 = 0.f, s2 = 0.f, s3 = 0.f;
#pragma unroll
        for (int i = 0; i < 16; i += 4) {
            s0 += sb[i + 0]; s1 += sb[i + 1]; s2 += sb[i + 2]; s3 += sb[i + 3];
        }
        ssum[split] = (s0 + s1) + (s2 + s3);
    }
    __syncthreads();

    if (split == 0 && lane < 50) {   // c = 2*lane in [0, 100)
        float2 a0 = so[0][lane], a1 = so[1][lane], a2 = so[2][lane], a3 = so[3][lane];
        float2 a4 = so[4][lane], a5 = so[5][lane], a6 = so[6][lane], a7 = so[7][lane];
        float ox = ((a0.x + a1.x) + (a2.x + a3.x)) + ((a4.x + a5.x) + (a6.x + a7.x));
        float oy = ((a0.y + a1.y) + (a2.y + a3.y)) + ((a4.y + a5.y) + (a6.y + a7.y));
        float st = ((ssum[0] + ssum[1]) + (ssum[2] + ssum[3]))
                 + ((ssum[4] + ssum[5]) + (ssum[6] + ssum[7]));
        float inv = 1.0f / st;
        *(float2*)(out + b * NCq + 2 * lane) = make_float2(ox * inv, oy * inv);
    }
}

// ============================ launch ============================
extern "C" void kernel_launch(void* const* d_in, const int* in_sizes, int n_in,
                              void* d_out, int out_size) {
    (void)in_sizes; (void)n_in; (void)out_size;
    const float* X = (const float*)d_in[0];   // [128,128]
    const float* A = (const float*)d_in[1];   // [16384,1,128]
    const float* C = (const float*)d_in[2];   // [16384,100]
    float* out = (float*)d_out;               // [128,100] fp32

    cudaFuncSetAttribute(main_kernel,
                         cudaFuncAttributeMaxDynamicSharedMemorySize, SMEM_BYTES);

    main_kernel<<<NBLKS, 512, SMEM_BYTES>>>(X, A, C);
    reduce_kernel<<<128, 512>>>(out);
}